// round 10
// baseline (speedup 1.0000x reference)
#include <cuda_runtime.h>
#include <cuda_fp16.h>
#include <cstdint>

// ============================================================================
// Problem: x[4, 4096, 2048]; Wi/Wf/Wg/Wo [2048, 2048]; w_norm [2048]; fp32.
// Pipeline: fp32->fp16 convert (w_norm folded into Wo) -> fp16 GEMM(i|f|g)
//           with gate activations fused into the epilogue (si / a / sg) ->
//           pure-FMA chunked linear scan -> warp-per-row sumsq ->
//           fp16 GEMM(out) with fused RMS row-scale epilogue.
// GEMM: m16n8k16 HMMA, tile 128x128x64, 3-stage cp.async, 2 CTAs/SM
//       (measured at ~the legacy-HMMA issue floor, ~525 TF/s).
// ============================================================================
constexpr int BB = 4;
constexpr int SS = 4096;
constexpr int DD = 2048;
constexpr int RM = BB * SS;                 // 16384 rows
constexpr size_t PLANE = (size_t)RM * DD;   // 33,554,432 elements

constexpr int TC  = 64;                     // scan chunk length
constexpr int NCH = SS / TC;                // 64 chunks
constexpr int DP  = DD / 2;                 // 1024 channel pairs

// ---------------------------------------------------------------------------
// Device scratch (static; allocations are forbidden)
// ---------------------------------------------------------------------------
__device__ __half g_proj[3 * PLANE];        // si, a, sg planes (fp16)
__device__ __half g_xh[PLANE];              // x in fp16
__device__ __half g_wh[3 * (size_t)DD * DD];// Wi|Wf|Wg in fp16 (concat rows)
__device__ __half g_woh[(size_t)DD * DD];   // Wo * w_norm in fp16
__device__ __half g_xgh[PLANE];             // xg in fp16 (GEMM2 A)
__device__ float  g_carryA[BB * NCH * DD];
__device__ float  g_carryB[BB * NCH * DD];
__device__ float  g_h0[BB * NCH * DD];
__device__ float  g_sumsq[RM];

// ---------------------------------------------------------------------------
// PTX helpers (sm_80-era only — safe under virtual arch compute_103)
// ---------------------------------------------------------------------------
__device__ __forceinline__ uint32_t smem_u32(const void* p) {
    uint32_t a;
    asm("{ .reg .u64 t; cvta.to.shared.u64 t, %1; cvt.u32.u64 %0, t; }"
        : "=r"(a) : "l"(p));
    return a;
}

#define CP_ASYNC16(dst, src) \
    asm volatile("cp.async.cg.shared.global [%0], [%1], 16;" \
                 :: "r"(dst), "l"(src))
#define CP_COMMIT() asm volatile("cp.async.commit_group;" ::: "memory")
#define CP_WAIT(n)  asm volatile("cp.async.wait_group %0;" :: "n"(n) : "memory")

__device__ __forceinline__ void ldsm4(uint32_t& r0, uint32_t& r1,
                                      uint32_t& r2, uint32_t& r3, uint32_t a) {
    asm volatile("ldmatrix.sync.aligned.m8n8.x4.shared.b16 {%0,%1,%2,%3}, [%4];"
                 : "=r"(r0), "=r"(r1), "=r"(r2), "=r"(r3) : "r"(a));
}

// D(16x8) += A(16x16) * B(16x8), fp16 inputs, fp32 accumulate.
__device__ __forceinline__ void mma16(float* c, const uint32_t* a,
                                      uint32_t b0, uint32_t b1) {
    asm volatile(
        "mma.sync.aligned.m16n8k16.row.col.f32.f16.f16.f32 "
        "{%0,%1,%2,%3}, {%4,%5,%6,%7}, {%8,%9}, {%0,%1,%2,%3};"
        : "+f"(c[0]), "+f"(c[1]), "+f"(c[2]), "+f"(c[3])
        : "r"(a[0]), "r"(a[1]), "r"(a[2]), "r"(a[3]), "r"(b0), "r"(b1));
}

__device__ __forceinline__ float sigmoidf_(float v) {
    return 1.0f / (1.0f + __expf(-v));
}

// ---------------------------------------------------------------------------
// fp16 GEMM: C[m,n] = sum_k A[m,k]*B[n,k], A,B row-major fp16.
// CTA tile 128x128x64, 256 threads, 8 warps of 32x64, 3-stage cp.async,
// 2 CTAs/SM (one CTA's sync/epilogue overlaps the other's MMAs).
// MODE 0: A=g_xh, B=g_wh; epilogue applies the gate activation per plane
//         (MUFU hidden under the tensor pipe) and stores si / a / sg fp16.
// MODE 1: A=g_xgh, B=g_woh; epilogue scales each row by rsqrt(mean sumsq+eps).
// ---------------------------------------------------------------------------
constexpr int MT = 128, NT = 128, KT = 64;
constexpr int NSLAB  = DD / KT;             // 32
constexpr int STAGES = 3;
constexpr int A_BYTES = MT * KT * 2;        // 16 KB (rows of 128 B)
constexpr int B_BYTES = NT * KT * 2;        // 16 KB
constexpr int STAGE_BYTES = A_BYTES + B_BYTES;       // 32 KB
constexpr int SMEM_BYTES  = STAGES * STAGE_BYTES;    // 96 KB

template <int MODE>
__global__ void __launch_bounds__(256, 2) gemm_f16_kernel(float* __restrict__ out) {
    extern __shared__ char sm[];
    const uint32_t smb = smem_u32(sm);
    const int tid  = threadIdx.x;
    const int lane = tid & 31, gid = lane >> 2, tig = lane & 3;
    const int wid  = tid >> 5, wm = wid & 3, wn = wid >> 2;

    const int n0 = blockIdx.x * NT;     // N fastest
    const int m0 = blockIdx.y * MT;

    const __half* Ap = (MODE == 0 ? g_xh : g_xgh) + (size_t)m0 * DD;
    const __half* Bp = (MODE == 0 ? g_wh : g_woh) + (size_t)n0 * DD;

    auto issue = [&](int s) {
        const int k0 = s * KT;
        const uint32_t sb = smb + (uint32_t)((s % STAGES) * STAGE_BYTES);
#pragma unroll
        for (int i = 0; i < 4; i++) {                 // A: 128 rows x 8 chunks
            const int idx = tid + i * 256;
            const int row = idx >> 3, ch = idx & 7;
            CP_ASYNC16(sb + row * 128 + (((uint32_t)(ch ^ (row & 7))) << 4),
                       Ap + (size_t)row * DD + k0 + ch * 8);
        }
#pragma unroll
        for (int i = 0; i < 4; i++) {                 // B: 128 rows x 8 chunks
            const int idx = tid + i * 256;
            const int row = idx >> 3, ch = idx & 7;
            CP_ASYNC16(sb + A_BYTES + row * 128 +
                           (((uint32_t)(ch ^ (row & 7))) << 4),
                       Bp + (size_t)row * DD + k0 + ch * 8);
        }
        CP_COMMIT();
    };

    // Per-lane ldmatrix row assignments (fixed across the k loop)
    const int sel = lane >> 3, ro = lane & 7;
    const int a_row_off = ((sel & 1) << 3) + ro;      // + mt*16 + wm*32
    const int a_cbit    = sel >> 1;
    const int b_row_off = ((sel >> 1) << 3) + ro;     // + ntp*16 + wn*64
    const int b_cbit    = sel & 1;

    float c[2][8][4];
#pragma unroll
    for (int i = 0; i < 2; i++)
#pragma unroll
        for (int j = 0; j < 8; j++)
#pragma unroll
            for (int q = 0; q < 4; q++) c[i][j][q] = 0.0f;

    issue(0); issue(1);

    for (int s = 0; s < NSLAB; s++) {
        CP_WAIT(1);
        __syncthreads();
        if (s + 2 < NSLAB) issue(s + 2);

        const uint32_t As = smb + (s % STAGES) * STAGE_BYTES;
        const uint32_t Bs = As + A_BYTES;
#pragma unroll
        for (int ks = 0; ks < 4; ks++) {              // 4 x K16 = KT 64
            uint32_t af[2][4], bf[8][2];
#pragma unroll
            for (int mt = 0; mt < 2; mt++) {
                const int row = wm * 32 + mt * 16 + a_row_off;
                const int ch  = (2 * ks + a_cbit) ^ (row & 7);
                ldsm4(af[mt][0], af[mt][1], af[mt][2], af[mt][3],
                      As + row * 128 + (ch << 4));
            }
#pragma unroll
            for (int ntp = 0; ntp < 4; ntp++) {
                const int row = wn * 64 + ntp * 16 + b_row_off;
                const int ch  = (2 * ks + b_cbit) ^ (row & 7);
                ldsm4(bf[2 * ntp][0], bf[2 * ntp][1],
                      bf[2 * ntp + 1][0], bf[2 * ntp + 1][1],
                      Bs + row * 128 + (ch << 4));
            }
#pragma unroll
            for (int mt = 0; mt < 2; mt++)
#pragma unroll
                for (int nt = 0; nt < 8; nt++)
                    mma16(c[mt][nt], af[mt], bf[nt][0], bf[nt][1]);
        }
    }

    // Epilogue: c[mt][nt] covers rows (gid, gid+8), cols (2tig, 2tig+1)
#pragma unroll
    for (int mt = 0; mt < 2; mt++) {
        const int r1 = m0 + wm * 32 + mt * 16 + gid;
        const int r2 = r1 + 8;
        float s1 = 1.0f, s2 = 1.0f;
        if (MODE == 1) {
            s1 = rsqrtf(g_sumsq[r1] * (1.0f / DD) + 1e-5f);
            s2 = rsqrtf(g_sumsq[r2] * (1.0f / DD) + 1e-5f);
        }
#pragma unroll
        for (int nt = 0; nt < 8; nt++) {
            const int cg = n0 + wn * 64 + nt * 8 + 2 * tig;
            if (MODE == 0) {
                const int ws = cg >> 11;              // 0:i  1:f  2:g
                float v[4];
#pragma unroll
                for (int q = 0; q < 4; q++) {
                    const float raw = c[mt][nt][q];
                    const float sg  = sigmoidf_(raw);
                    v[q] = (ws == 1) ? sg : raw * sg; // a  or  silu
                }
                __half* base = g_proj + (size_t)ws * PLANE + (cg & (DD - 1));
                *reinterpret_cast<__half2*>(base + (size_t)r1 * DD) =
                    __floats2half2_rn(v[0], v[1]);
                *reinterpret_cast<__half2*>(base + (size_t)r2 * DD) =
                    __floats2half2_rn(v[2], v[3]);
            } else {
                *reinterpret_cast<float2*>(out + (size_t)r1 * DD + cg) =
                    make_float2(c[mt][nt][0] * s1, c[mt][nt][1] * s1);
                *reinterpret_cast<float2*>(out + (size_t)r2 * DD + cg) =
                    make_float2(c[mt][nt][2] * s2, c[mt][nt][3] * s2);
            }
        }
    }
}

// ---------------------------------------------------------------------------
// fp32 -> fp16 conversion: 16 elements/thread, 4 independent float4 loads.
// Wo (m==3) is multiplied by w_norm[col] during conversion.
// ---------------------------------------------------------------------------
__global__ void __launch_bounds__(256) f2h_x_kernel(const float* __restrict__ src,
                                                    __half* __restrict__ dst) {
    const size_t i = ((size_t)blockIdx.x * 256 + threadIdx.x) * 16;
    float4 v[4];
#pragma unroll
    for (int j = 0; j < 4; j++)
        v[j] = *reinterpret_cast<const float4*>(src + i + j * 4);
#pragma unroll
    for (int j = 0; j < 4; j++) {
        __half2 h[2];
        h[0] = __floats2half2_rn(v[j].x, v[j].y);
        h[1] = __floats2half2_rn(v[j].z, v[j].w);
        *reinterpret_cast<uint2*>(dst + i + j * 4) = *reinterpret_cast<uint2*>(h);
    }
}

__global__ void __launch_bounds__(256) f2h_w_kernel(
    const float* __restrict__ w0, const float* __restrict__ w1,
    const float* __restrict__ w2, const float* __restrict__ w3,
    const float* __restrict__ wn) {
    const size_t i = ((size_t)blockIdx.x * 256 + threadIdx.x) * 16;
    const int m = blockIdx.y;
    const float* src = (m == 0) ? w0 : (m == 1) ? w1 : (m == 2) ? w2 : w3;
    __half* dst = (m < 3) ? (g_wh + (size_t)m * DD * DD) : g_woh;
    float4 v[4];
#pragma unroll
    for (int j = 0; j < 4; j++)
        v[j] = *reinterpret_cast<const float4*>(src + i + j * 4);
    if (m == 3) {                                     // fold w_norm into Wo
        const int e0 = (int)(i & (DD - 1));
#pragma unroll
        for (int j = 0; j < 4; j++) {
            float4 w = *reinterpret_cast<const float4*>(wn + e0 + j * 4);
            v[j].x *= w.x; v[j].y *= w.y; v[j].z *= w.z; v[j].w *= w.w;
        }
    }
#pragma unroll
    for (int j = 0; j < 4; j++) {
        __half2 h[2];
        h[0] = __floats2half2_rn(v[j].x, v[j].y);
        h[1] = __floats2half2_rn(v[j].z, v[j].w);
        *reinterpret_cast<uint2*>(dst + i + j * 4) = *reinterpret_cast<uint2*>(h);
    }
}

// ---------------------------------------------------------------------------
// Scan: h_t = a_t h_{t-1} + b_t with b = si*(1-a); planes hold si / a / sg.
// Pure FMA + loads. Each thread owns a pair of adjacent channels (half2).
// ---------------------------------------------------------------------------
__global__ void __launch_bounds__(256) scan_chunk_kernel() {
    const int gid = blockIdx.x * 256 + threadIdx.x;   // (b, c, dp)
    const int dp = gid & (DP - 1);
    const int c  = (gid >> 10) & (NCH - 1);
    const int b  = gid >> 16;                         // 10 + 6
    const size_t rb = ((size_t)(b * SS + c * TC)) * DD + dp * 2;
    const __half2* Sp = reinterpret_cast<const __half2*>(g_proj + rb);
    const __half2* Ap = reinterpret_cast<const __half2*>(g_proj + PLANE + rb);
    float A0 = 1.0f, B0 = 0.0f, A1 = 1.0f, B1 = 0.0f;
    for (int t0 = 0; t0 < TC; t0 += 8) {
        __half2 sh[8], ah[8];
#pragma unroll
        for (int j = 0; j < 8; j++) {
            sh[j] = Sp[(size_t)(t0 + j) * DP];
            ah[j] = Ap[(size_t)(t0 + j) * DP];
        }
#pragma unroll
        for (int j = 0; j < 8; j++) {
            const float2 si = __half22float2(sh[j]);
            const float2 av = __half22float2(ah[j]);
            A0 *= av.x; A1 *= av.y;
            B0 = fmaf(av.x, B0, si.x * (1.0f - av.x));
            B1 = fmaf(av.y, B1, si.y * (1.0f - av.y));
        }
    }
    const int idx = ((b * NCH + c) << 11) + dp * 2;   // (b,c,d) float index
    *reinterpret_cast<float2*>(g_carryA + idx) = make_float2(A0, A1);
    *reinterpret_cast<float2*>(g_carryB + idx) = make_float2(B0, B1);
}

__global__ void __launch_bounds__(256) scan_prefix_kernel() {
    const int id = blockIdx.x * 256 + threadIdx.x;    // (b, dp)
    const int dp = id & (DP - 1);
    const int b  = id >> 10;
    float2 h = make_float2(0.0f, 0.0f);
#pragma unroll
    for (int c = 0; c < NCH; c++) {
        const int idx = ((b * NCH + c) << 11) + dp * 2;
        *reinterpret_cast<float2*>(g_h0 + idx) = h;
        const float2 A = *reinterpret_cast<const float2*>(g_carryA + idx);
        const float2 Bc = *reinterpret_cast<const float2*>(g_carryB + idx);
        h.x = fmaf(A.x, h.x, Bc.x);
        h.y = fmaf(A.y, h.y, Bc.y);
    }
}

__global__ void __launch_bounds__(256) scan_apply_kernel() {
    const int gid = blockIdx.x * 256 + threadIdx.x;   // (b, c, dp)
    const int dp = gid & (DP - 1);
    const int c  = (gid >> 10) & (NCH - 1);
    const int b  = gid >> 16;
    const size_t rb = ((size_t)(b * SS + c * TC)) * DD + dp * 2;
    const __half2* Sp = reinterpret_cast<const __half2*>(g_proj + rb);
    const __half2* Ap = reinterpret_cast<const __half2*>(g_proj + PLANE + rb);
    const __half2* Gp = reinterpret_cast<const __half2*>(g_proj + 2 * PLANE + rb);
    __half2* Xp = reinterpret_cast<__half2*>(g_xgh + rb);
    const float2 h0v = *reinterpret_cast<const float2*>(
        g_h0 + ((b * NCH + c) << 11) + dp * 2);
    float h0 = h0v.x, h1 = h0v.y;
    for (int t0 = 0; t0 < TC; t0 += 8) {
        __half2 sh[8], ah[8], gh[8];
#pragma unroll
        for (int j = 0; j < 8; j++) {
            sh[j] = Sp[(size_t)(t0 + j) * DP];
            ah[j] = Ap[(size_t)(t0 + j) * DP];
            gh[j] = Gp[(size_t)(t0 + j) * DP];
        }
#pragma unroll
        for (int j = 0; j < 8; j++) {
            const float2 si = __half22float2(sh[j]);
            const float2 av = __half22float2(ah[j]);
            const float2 sg = __half22float2(gh[j]);
            h0 = fmaf(av.x, h0, si.x * (1.0f - av.x));
            h1 = fmaf(av.y, h1, si.y * (1.0f - av.y));
            Xp[(size_t)(t0 + j) * DP] = __floats2half2_rn(h0 * sg.x, h1 * sg.y);
        }
    }
}

// ---------------------------------------------------------------------------
// Per-row sum of squares of xg: one warp per row (coalesced half2, MLP 32)
// ---------------------------------------------------------------------------
__global__ void __launch_bounds__(256) rowsumsq_kernel() {
    const int r = blockIdx.x * 8 + (threadIdx.x >> 5);
    const int lane = threadIdx.x & 31;
    const __half2* p = reinterpret_cast<const __half2*>(g_xgh + (size_t)r * DD);
    float s = 0.0f;
#pragma unroll
    for (int k = 0; k < 32; k++) {
        const float2 v = __half22float2(p[lane + k * 32]);
        s = fmaf(v.x, v.x, fmaf(v.y, v.y, s));
    }
#pragma unroll
    for (int o = 16; o; o >>= 1) s += __shfl_xor_sync(0xffffffffu, s, o);
    if (lane == 0) g_sumsq[r] = s;
}

// ---------------------------------------------------------------------------
// Launcher
// ---------------------------------------------------------------------------
extern "C" void kernel_launch(void* const* d_in, const int* in_sizes, int n_in,
                              void* d_out, int out_size) {
    const float* x  = (const float*)d_in[0];
    const float* Wi = (const float*)d_in[1];
    const float* Wf = (const float*)d_in[2];
    const float* Wg = (const float*)d_in[3];
    const float* wn = (const float*)d_in[4];
    const float* Wo = (const float*)d_in[5];
    float* out = (float*)d_out;

    cudaFuncSetAttribute(gemm_f16_kernel<0>,
                         cudaFuncAttributeMaxDynamicSharedMemorySize, SMEM_BYTES);
    cudaFuncSetAttribute(gemm_f16_kernel<1>,
                         cudaFuncAttributeMaxDynamicSharedMemorySize, SMEM_BYTES);

    __half* xh;  cudaGetSymbolAddress((void**)&xh, g_xh);

    // 0) fp32 -> fp16 conversions (w_norm folded into Wo)
    constexpr int WEL = DD * DD;             // 4,194,304
    f2h_x_kernel<<<PLANE / 4096, 256>>>(x, xh);
    f2h_w_kernel<<<dim3(WEL / 4096, 4), 256>>>(Wi, Wf, Wg, Wo, wn);

    // 1) Fused projection GEMM (N = 6144 concat) + gate activations in epilogue
    dim3 g1(3 * DD / NT, RM / MT);   // (48, 128), N fastest
    gemm_f16_kernel<0><<<g1, 256, SMEM_BYTES>>>(nullptr);

    // 2) Pure-FMA chunked linear scan
    scan_chunk_kernel<<<(BB * NCH * DP) / 256, 256>>>();
    scan_prefix_kernel<<<(BB * DP) / 256, 256>>>();
    scan_apply_kernel<<<(BB * NCH * DP) / 256, 256>>>();
    rowsumsq_kernel<<<RM / 8, 256>>>();

    // 3) Output GEMM with fused RMSNorm row scaling (Wo pre-scaled by w_norm)
    dim3 g2(DD / NT, RM / MT);       // (16, 128), N fastest
    gemm_f16_kernel<1><<<g2, 256, SMEM_BYTES>>>(out);
}